// round 3
// baseline (speedup 1.0000x reference)
#include <cuda_runtime.h>

#define BB 2
#define SS 2048
#define DD 1024
#define HH 16
#define DKK 64
#define KSPLIT 16

// ---------------- device scratch ----------------
__device__ float g_qs[(size_t)BB*HH*SS*DKK];   // tf32-rounded, scaled by log2e/8
__device__ float g_ks[(size_t)BB*HH*SS*DKK];   // tf32-rounded
__device__ float g_vs[(size_t)BB*SS*DKK];
__device__ float g_w [(size_t)BB*HH*SS];       // 1/(H * rowsum)
__device__ float g_headp[(size_t)KSPLIT*BB*SS*DKK];
__device__ float g_head [(size_t)BB*SS*DKK];

// ---------------- helpers ----------------
__device__ __forceinline__ float ex2(float x) {
    float y; asm("ex2.approx.f32 %0, %1;" : "=f"(y) : "f"(x)); return y;
}
__device__ __forceinline__ float to_tf32(float x) {
    unsigned u; asm("cvt.rna.tf32.f32 %0, %1;" : "=r"(u) : "f"(x));
    return __uint_as_float(u);
}
__device__ __forceinline__ void mma_tf32(float c[4], const unsigned a[4], const unsigned b[2]) {
    asm volatile(
        "mma.sync.aligned.m16n8k8.row.col.f32.tf32.tf32.f32 "
        "{%0,%1,%2,%3}, {%4,%5,%6,%7}, {%8,%9}, {%0,%1,%2,%3};\n"
        : "+f"(c[0]), "+f"(c[1]), "+f"(c[2]), "+f"(c[3])
        : "r"(a[0]), "r"(a[1]), "r"(a[2]), "r"(a[3]), "r"(b[0]), "r"(b[1]));
}
__device__ __forceinline__ void cp16(float* dst_smem, const float* src) {
    unsigned d = (unsigned)__cvta_generic_to_shared(dst_smem);
    asm volatile("cp.async.ca.shared.global [%0], [%1], 16;\n" :: "r"(d), "l"(src));
}
#define CP_COMMIT() asm volatile("cp.async.commit_group;\n")
#define CP_WAIT1()  asm volatile("cp.async.wait_group 1;\n")

// ================= K1: Q/K projections as dense GEMM (tf32 MMA) =================
__global__ void k_proj_mma(const float* __restrict__ q, const float* __restrict__ k,
                           const float* __restrict__ Wq, const float* __restrict__ Wk) {
    extern __shared__ float sm[];
    float (*As)[36]  = (float(*)[36])sm;
    float (*Bs)[136] = (float(*)[136])(sm + 128*36);

    int kind = blockIdx.z >> 1;
    int b    = blockIdx.z & 1;
    int h0   = blockIdx.x * 2;
    int s0   = blockIdx.y * 128;

    const float* A = (kind ? k : q) + (size_t)b*SS*DD;
    const float* W = kind ? Wk : Wq;
    float* C       = kind ? g_ks : g_qs;
    float scale    = kind ? 1.0f : (1.4426950408889634f / 8.0f);

    int tid = threadIdx.x;
    int w = tid >> 5, lane = tid & 31;
    int wm = w >> 1, wn = w & 1;
    int g = lane >> 2, tg = lane & 3;

    float c[2][8][4] = {};

    for (int k0 = 0; k0 < DD; k0 += 32) {
        #pragma unroll
        for (int i = 0; i < 4; i++) {
            int f = tid + i * 256;
            int row = f >> 3, c4 = (f & 7) * 4;
            *(float4*)&As[row][c4] = *(const float4*)&A[(size_t)(s0 + row) * DD + k0 + c4];
        }
        #pragma unroll
        for (int i = 0; i < 4; i++) {
            int f = tid + i * 256;
            int kk = f >> 5, n4 = (f & 31) * 4;
            int hh = h0 + (n4 >> 6), dk = n4 & 63;
            *(float4*)&Bs[kk][n4] = *(const float4*)&W[((size_t)hh * DD + k0 + kk) * DKK + dk];
        }
        __syncthreads();
        #pragma unroll
        for (int ks = 0; ks < 32; ks += 8) {
            unsigned a[2][4];
            #pragma unroll
            for (int mf = 0; mf < 2; mf++) {
                int r = wm * 32 + mf * 16 + g;
                a[mf][0] = __float_as_uint(As[r    ][ks + tg]);
                a[mf][1] = __float_as_uint(As[r + 8][ks + tg]);
                a[mf][2] = __float_as_uint(As[r    ][ks + tg + 4]);
                a[mf][3] = __float_as_uint(As[r + 8][ks + tg + 4]);
            }
            unsigned bfr[8][2];
            #pragma unroll
            for (int nf = 0; nf < 8; nf++) {
                int n = wn * 64 + nf * 8 + g;
                bfr[nf][0] = __float_as_uint(Bs[ks + tg    ][n]);
                bfr[nf][1] = __float_as_uint(Bs[ks + tg + 4][n]);
            }
            #pragma unroll
            for (int mf = 0; mf < 2; mf++)
                #pragma unroll
                for (int nf = 0; nf < 8; nf++)
                    mma_tf32(c[mf][nf], a[mf], bfr[nf]);
        }
        __syncthreads();
    }
    int hh = h0 + wn;
    #pragma unroll
    for (int mf = 0; mf < 2; mf++) {
        int r = s0 + wm * 32 + mf * 16 + g;
        #pragma unroll
        for (int nf = 0; nf < 8; nf++) {
            int dk = nf * 8 + 2 * tg;
            float* p0 = &C[((size_t)(b * HH + hh) * SS + r) * DKK + dk];
            float* p1 = &C[((size_t)(b * HH + hh) * SS + r + 8) * DKK + dk];
            *(float2*)p0 = make_float2(to_tf32(c[mf][nf][0] * scale), to_tf32(c[mf][nf][1] * scale));
            *(float2*)p1 = make_float2(to_tf32(c[mf][nf][2] * scale), to_tf32(c[mf][nf][3] * scale));
        }
    }
}

// ================= K1b: V projection (small, SIMT) =================
__global__ void k_projv(const float* __restrict__ v, const float* __restrict__ Wv) {
    int b  = blockIdx.z;
    int s0 = blockIdx.x * 64;
    const float* A = v + (size_t)b*SS*DD;
    float* C = g_vs + (size_t)b*SS*DKK;

    __shared__ float As[16][64];
    __shared__ float Ws[16][64];
    int tid = threadIdx.x;
    int tx = tid & 15, ty = tid >> 4;
    float acc[4][4] = {};

    for (int k0 = 0; k0 < DD; k0 += 16) {
        {
            int row = tid >> 2, kk4 = (tid & 3) * 4;
            float4 av = *(const float4*)&A[(size_t)(s0 + row) * DD + k0 + kk4];
            As[kk4+0][row] = av.x; As[kk4+1][row] = av.y;
            As[kk4+2][row] = av.z; As[kk4+3][row] = av.w;
        }
        {
            int kk = tid >> 4, c4 = (tid & 15) * 4;
            *(float4*)&Ws[kk][c4] = *(const float4*)&Wv[(size_t)(k0 + kk) * DKK + c4];
        }
        __syncthreads();
        #pragma unroll
        for (int kk = 0; kk < 16; kk++) {
            float4 a  = *(const float4*)&As[kk][ty * 4];
            float4 bb = *(const float4*)&Ws[kk][tx * 4];
            float av[4] = {a.x, a.y, a.z, a.w};
            float bv[4] = {bb.x, bb.y, bb.z, bb.w};
            #pragma unroll
            for (int i = 0; i < 4; i++)
                #pragma unroll
                for (int j = 0; j < 4; j++)
                    acc[i][j] = fmaf(av[i], bv[j], acc[i][j]);
        }
        __syncthreads();
    }
    #pragma unroll
    for (int i = 0; i < 4; i++) {
        float4 o; o.x = acc[i][0]; o.y = acc[i][1]; o.z = acc[i][2]; o.w = acc[i][3];
        *(float4*)&C[(size_t)(s0 + ty * 4 + i) * DKK + tx * 4] = o;
    }
}

// ================= K2: pass 1 — rowsums of exp2(scores), pipelined =================
// grid: x = s_tile(16, 128 rows), y = h, z = b. Q resident; K streamed in 32-wide chunks.
__global__ void k_rowsum() {
    extern __shared__ float sm[];
    float (*Qs)[68]    = (float(*)[68])sm;                    // [128][68]
    float (*Kb)[128][36] = (float(*)[128][36])(sm + 128*68);  // [2][128][36]
    float* red         = sm;                                  // reuse after loop (safe: post-sync)

    int b = blockIdx.z, h = blockIdx.y;
    int s0 = blockIdx.x * 128;
    int tid = threadIdx.x;
    int w = tid >> 5, lane = tid & 31;
    int wm = w >> 1, wn = w & 1;
    int g = lane >> 2, tg = lane & 3;

    const float* Qsrc = g_qs + ((size_t)(b*HH + h)*SS + s0) * DKK;
    const float* Kbase = g_ks + ((size_t)(b*HH + h)*SS) * DKK;

    // Q tile 128x64 resident
    #pragma unroll
    for (int i = 0; i < 8; i++) {
        int f = tid + i * 256;
        int row = f >> 4, c4 = (f & 15) * 4;
        *(float4*)&Qs[row][c4] = *(const float4*)&Qsrc[(size_t)row * DKK + c4];
    }

    const int NC = (SS / 128) * 2;   // 32 chunks: (t-tile, k-half)
    // issue chunk c into buffer c&1
    auto issue = [&](int c) {
        int tt = c >> 1, kh = c & 1;
        const float* src = Kbase + ((size_t)tt * 128) * DKK + kh * 32;
        int buf = c & 1;
        #pragma unroll
        for (int i = 0; i < 4; i++) {
            int f = tid + i * 256;
            int row = f >> 3, c4 = (f & 7) * 4;
            cp16(&Kb[buf][row][c4], src + (size_t)row * DKK + c4);
        }
    };
    issue(0); CP_COMMIT();
    issue(1); CP_COMMIT();

    float sc[2][8][4];
    float rs[2][2] = {};

    for (int c = 0; c < NC; c++) {
        CP_WAIT1();
        __syncthreads();
        int buf = c & 1, kh = c & 1;
        if (kh == 0) {
            #pragma unroll
            for (int mf = 0; mf < 2; mf++)
                #pragma unroll
                for (int nf = 0; nf < 8; nf++)
                    #pragma unroll
                    for (int i = 0; i < 4; i++) sc[mf][nf][i] = 0.f;
        }
        #pragma unroll
        for (int ks = 0; ks < 32; ks += 8) {
            unsigned a[2][4];
            #pragma unroll
            for (int mf = 0; mf < 2; mf++) {
                int r = wm * 32 + mf * 16 + g;
                int kg = kh * 32 + ks + tg;
                a[mf][0] = __float_as_uint(Qs[r    ][kg]);
                a[mf][1] = __float_as_uint(Qs[r + 8][kg]);
                a[mf][2] = __float_as_uint(Qs[r    ][kg + 4]);
                a[mf][3] = __float_as_uint(Qs[r + 8][kg + 4]);
            }
            unsigned bfr[8][2];
            #pragma unroll
            for (int nf = 0; nf < 8; nf++) {
                int t = wn * 64 + nf * 8 + g;
                bfr[nf][0] = __float_as_uint(Kb[buf][t][ks + tg]);
                bfr[nf][1] = __float_as_uint(Kb[buf][t][ks + tg + 4]);
            }
            #pragma unroll
            for (int mf = 0; mf < 2; mf++)
                #pragma unroll
                for (int nf = 0; nf < 8; nf++)
                    mma_tf32(sc[mf][nf], a[mf], bfr[nf]);
        }
        if (kh == 1) {
            #pragma unroll
            for (int mf = 0; mf < 2; mf++)
                #pragma unroll
                for (int nf = 0; nf < 8; nf++) {
                    rs[mf][0] += ex2(sc[mf][nf][0]) + ex2(sc[mf][nf][1]);
                    rs[mf][1] += ex2(sc[mf][nf][2]) + ex2(sc[mf][nf][3]);
                }
        }
        __syncthreads();
        if (c + 2 < NC) issue(c + 2);
        CP_COMMIT();
    }

    #pragma unroll
    for (int mf = 0; mf < 2; mf++)
        #pragma unroll
        for (int i = 0; i < 2; i++) {
            float s = rs[mf][i];
            s += __shfl_xor_sync(0xffffffffu, s, 1);
            s += __shfl_xor_sync(0xffffffffu, s, 2);
            rs[mf][i] = s;
        }
    __syncthreads();
    if (tg == 0) {
        #pragma unroll
        for (int mf = 0; mf < 2; mf++)
            #pragma unroll
            for (int i = 0; i < 2; i++)
                red[wn * 128 + wm * 32 + mf * 16 + g + 8 * i] = rs[mf][i];
    }
    __syncthreads();
    if (tid < 128) {
        float s = red[tid] + red[128 + tid];
        g_w[(size_t)(b*HH + h)*SS + s0 + tid] = 1.0f / (s * (float)HH);
    }
}

// ================= K3: pass 2 — attn_mean, pipelined over (head, k-half) =================
// grid: x = t_tile(32, 64 cols), y = s_tile(16, 128 rows), z = b
__global__ void k_attn(float* __restrict__ out) {
    extern __shared__ float sm[];
    float (*Qb)[128][36] = (float(*)[128][36])sm;                 // [2][128][36]
    float (*Kb)[64][36]  = (float(*)[64][36])(sm + 2*128*36);     // [2][64][36]

    int b = blockIdx.z;
    int s0 = blockIdx.y * 128;
    int t0 = blockIdx.x * 64;
    int tid = threadIdx.x;
    int w = tid >> 5, lane = tid & 31;
    int wm = w >> 1, wn = w & 1;
    int g = lane >> 2, tg = lane & 3;

    const int NC = HH * 2;
    auto issue = [&](int c) {
        int h = c >> 1, kh = c & 1;
        const float* Qsrc = g_qs + ((size_t)(b*HH + h)*SS + s0) * DKK + kh * 32;
        const float* Ksrc = g_ks + ((size_t)(b*HH + h)*SS + t0) * DKK + kh * 32;
        int buf = c & 1;
        #pragma unroll
        for (int i = 0; i < 4; i++) {
            int f = tid + i * 256;
            int row = f >> 3, c4 = (f & 7) * 4;
            cp16(&Qb[buf][row][c4], Qsrc + (size_t)row * DKK + c4);
        }
        #pragma unroll
        for (int i = 0; i < 2; i++) {
            int f = tid + i * 256;
            int row = f >> 3, c4 = (f & 7) * 4;
            cp16(&Kb[buf][row][c4], Ksrc + (size_t)row * DKK + c4);
        }
    };
    issue(0); CP_COMMIT();
    issue(1); CP_COMMIT();

    float acc[2][4][4] = {};
    float sc[2][4][4];

    for (int c = 0; c < NC; c++) {
        CP_WAIT1();
        __syncthreads();
        int buf = c & 1, kh = c & 1;
        if (kh == 0) {
            #pragma unroll
            for (int mf = 0; mf < 2; mf++)
                #pragma unroll
                for (int nf = 0; nf < 4; nf++)
                    #pragma unroll
                    for (int i = 0; i < 4; i++) sc[mf][nf][i] = 0.f;
        }
        #pragma unroll
        for (int ks = 0; ks < 32; ks += 8) {
            unsigned a[2][4];
            #pragma unroll
            for (int mf = 0; mf < 2; mf++) {
                int r = wm * 32 + mf * 16 + g;
                a[mf][0] = __float_as_uint(Qb[buf][r    ][ks + tg]);
                a[mf][1] = __float_as_uint(Qb[buf][r + 8][ks + tg]);
                a[mf][2] = __float_as_uint(Qb[buf][r    ][ks + tg + 4]);
                a[mf][3] = __float_as_uint(Qb[buf][r + 8][ks + tg + 4]);
            }
            unsigned bfr[4][2];
            #pragma unroll
            for (int nf = 0; nf < 4; nf++) {
                int t = wn * 32 + nf * 8 + g;
                bfr[nf][0] = __float_as_uint(Kb[buf][t][ks + tg]);
                bfr[nf][1] = __float_as_uint(Kb[buf][t][ks + tg + 4]);
            }
            #pragma unroll
            for (int mf = 0; mf < 2; mf++)
                #pragma unroll
                for (int nf = 0; nf < 4; nf++)
                    mma_tf32(sc[mf][nf], a[mf], bfr[nf]);
        }
        if (kh == 1) {
            int h = c >> 1;
            float wv[2][2];
            #pragma unroll
            for (int mf = 0; mf < 2; mf++) {
                int r = s0 + wm * 32 + mf * 16 + g;
                wv[mf][0] = g_w[(size_t)(b*HH + h)*SS + r];
                wv[mf][1] = g_w[(size_t)(b*HH + h)*SS + r + 8];
            }
            #pragma unroll
            for (int mf = 0; mf < 2; mf++)
                #pragma unroll
                for (int nf = 0; nf < 4; nf++) {
                    acc[mf][nf][0] = fmaf(ex2(sc[mf][nf][0]), wv[mf][0], acc[mf][nf][0]);
                    acc[mf][nf][1] = fmaf(ex2(sc[mf][nf][1]), wv[mf][0], acc[mf][nf][1]);
                    acc[mf][nf][2] = fmaf(ex2(sc[mf][nf][2]), wv[mf][1], acc[mf][nf][2]);
                    acc[mf][nf][3] = fmaf(ex2(sc[mf][nf][3]), wv[mf][1], acc[mf][nf][3]);
                }
        }
        __syncthreads();
        if (c + 2 < NC) issue(c + 2);
        CP_COMMIT();
    }

    float* AM = out + (size_t)BB*SS*DD + ((size_t)b*SS) * SS;
    #pragma unroll
    for (int mf = 0; mf < 2; mf++) {
        int r = s0 + wm * 32 + mf * 16 + g;
        #pragma unroll
        for (int nf = 0; nf < 4; nf++) {
            int cc = t0 + wn * 32 + nf * 8 + 2 * tg;
            *(float2*)&AM[(size_t)r * SS + cc]       = make_float2(acc[mf][nf][0], acc[mf][nf][1]);
            *(float2*)&AM[(size_t)(r + 8) * SS + cc] = make_float2(acc[mf][nf][2], acc[mf][nf][3]);
        }
    }
}

// ================= K4: head partials = attn_mean @ vs (split-K) =================
__global__ void k_headp(const float* __restrict__ out) {
    int c = blockIdx.x;
    int s0 = blockIdx.y * 64;
    int b = blockIdx.z;
    int tb = c * (SS / KSPLIT);

    const float* AM = out + (size_t)BB*SS*DD + ((size_t)b*SS) * SS;
    const float* V  = g_vs + (size_t)b*SS*DKK;

    __shared__ float As[16][64];
    __shared__ float Vs[16][64];
    int tid = threadIdx.x;
    int tx = tid & 15, ty = tid >> 4;
    float acc[4][4] = {};

    for (int t0 = 0; t0 < SS / KSPLIT; t0 += 16) {
        {
            int row = tid >> 2, kk4 = (tid & 3) * 4;
            float4 av = *(const float4*)&AM[(size_t)(s0 + row) * SS + tb + t0 + kk4];
            As[kk4+0][row] = av.x; As[kk4+1][row] = av.y;
            As[kk4+2][row] = av.z; As[kk4+3][row] = av.w;
        }
        {
            int kk = tid >> 4, c4 = (tid & 15) * 4;
            *(float4*)&Vs[kk][c4] = *(const float4*)&V[(size_t)(tb + t0 + kk) * DKK + c4];
        }
        __syncthreads();
        #pragma unroll
        for (int kk = 0; kk < 16; kk++) {
            float4 a  = *(const float4*)&As[kk][ty * 4];
            float4 bb = *(const float4*)&Vs[kk][tx * 4];
            float av[4] = {a.x, a.y, a.z, a.w};
            float bv[4] = {bb.x, bb.y, bb.z, bb.w};
            #pragma unroll
            for (int i = 0; i < 4; i++)
                #pragma unroll
                for (int j = 0; j < 4; j++)
                    acc[i][j] = fmaf(av[i], bv[j], acc[i][j]);
        }
        __syncthreads();
    }
    float* C = g_headp + (((size_t)c*BB + b)*SS) * DKK;
    #pragma unroll
    for (int i = 0; i < 4; i++) {
        float4 o; o.x = acc[i][0]; o.y = acc[i][1]; o.z = acc[i][2]; o.w = acc[i][3];
        *(float4*)&C[(size_t)(s0 + ty * 4 + i) * DKK + tx * 4] = o;
    }
}

// ================= K5: reduce split-K partials =================
__global__ void k_reduce() {
    size_t i4 = (size_t)blockIdx.x * blockDim.x + threadIdx.x;
    size_t N4 = (size_t)BB*SS*DKK / 4;
    if (i4 >= N4) return;
    float4 s = make_float4(0.f, 0.f, 0.f, 0.f);
    #pragma unroll
    for (int c = 0; c < KSPLIT; c++) {
        float4 x = *((const float4*)g_headp + (size_t)c * N4 + i4);
        s.x += x.x; s.y += x.y; s.z += x.z; s.w += x.w;
    }
    *((float4*)g_head + i4) = s;
}

// ================= K6: out = head @ Wo =================
__global__ void k_out(const float* __restrict__ Wo, float* __restrict__ out) {
    int d0 = blockIdx.x * 64;
    int r0 = blockIdx.y * 64;
    __shared__ float Hs[64][64];
    __shared__ float Ws[64][64];
    int tid = threadIdx.x;
    int tx = tid & 15, ty = tid >> 4;

    {
        const float* src = g_head + (size_t)r0 * DKK;
        #pragma unroll
        for (int l = 0; l < 4; l++) {
            int f = tid + l * 256;
            int row = f >> 4, c4 = (f & 15) * 4;
            float4 x = *(const float4*)&src[(size_t)row * 64 + c4];
            Hs[c4+0][row] = x.x; Hs[c4+1][row] = x.y;
            Hs[c4+2][row] = x.z; Hs[c4+3][row] = x.w;
        }
    }
    #pragma unroll
    for (int l = 0; l < 4; l++) {
        int f = tid + l * 256;
        int kk = f >> 4, c4 = (f & 15) * 4;
        *(float4*)&Ws[kk][c4] = *(const float4*)&Wo[(size_t)kk * DD + d0 + c4];
    }
    __syncthreads();

    float acc[4][4] = {};
    #pragma unroll 16
    for (int kk = 0; kk < 64; kk++) {
        float4 a  = *(const float4*)&Hs[kk][ty * 4];
        float4 bb = *(const float4*)&Ws[kk][tx * 4];
        float av[4] = {a.x, a.y, a.z, a.w};
        float bv[4] = {bb.x, bb.y, bb.z, bb.w};
        #pragma unroll
        for (int i = 0; i < 4; i++)
            #pragma unroll
            for (int j = 0; j < 4; j++)
                acc[i][j] = fmaf(av[i], bv[j], acc[i][j]);
    }
    #pragma unroll
    for (int i = 0; i < 4; i++) {
        float4 o; o.x = acc[i][0]; o.y = acc[i][1]; o.z = acc[i][2]; o.w = acc[i][3];
        *(float4*)&out[(size_t)(r0 + ty * 4 + i) * DD + d0 + tx * 4] = o;
    }
}

// ================= launch =================
extern "C" void kernel_launch(void* const* d_in, const int* in_sizes, int n_in,
                              void* d_out, int out_size) {
    const float* q  = (const float*)d_in[0];
    const float* k  = (const float*)d_in[1];
    const float* v  = (const float*)d_in[2];
    const float* Wq = (const float*)d_in[3];
    const float* Wk = (const float*)d_in[4];
    const float* Wv = (const float*)d_in[5];
    const float* Wo = (const float*)d_in[6];
    float* out = (float*)d_out;

    const int smem_proj   = (128*36 + 32*136) * 4;
    const int smem_rowsum = (128*68 + 2*128*36) * 4;
    const int smem_attn   = (2*128*36 + 2*64*36) * 4;
    cudaFuncSetAttribute(k_proj_mma, cudaFuncAttributeMaxDynamicSharedMemorySize, smem_proj);
    cudaFuncSetAttribute(k_rowsum,   cudaFuncAttributeMaxDynamicSharedMemorySize, smem_rowsum);
    cudaFuncSetAttribute(k_attn,     cudaFuncAttributeMaxDynamicSharedMemorySize, smem_attn);

    dim3 gp(DD / 128, SS / 128, 4);
    k_proj_mma<<<gp, 256, smem_proj>>>(q, k, Wq, Wk);

    dim3 gv(SS / 64, 1, BB);
    k_projv<<<gv, 256>>>(v, Wv);

    dim3 gr(SS / 128, HH, BB);
    k_rowsum<<<gr, 256, smem_rowsum>>>();

    dim3 ga(SS / 64, SS / 128, BB);
    k_attn<<<ga, 256, smem_attn>>>(out);

    dim3 gh(KSPLIT, SS / 64, BB);
    k_headp<<<gh, 256>>>(out);

    int n4 = BB * SS * DKK / 4;
    k_reduce<<<(n4 + 255) / 256, 256>>>();

    dim3 go(DD / 64, BB * SS / 64);
    k_out<<<go, 256>>>(Wo, out);
}